// round 10
// baseline (speedup 1.0000x reference)
#include <cuda_runtime.h>
#include <cuda_bf16.h>
#include <math.h>
#include <stdint.h>

#define NB 16
#define NN 1024
#define MM 1024
#define DK 512

// -------- device scratch (no allocations allowed) --------
__device__ float g_U[NB * NN];
__device__ float g_V[NB * MM];
__device__ float g_W[NB * NN];
__device__ float g_WT[NB * 3 * NN];
__device__ float g_PM[NB * 64 * MM];
__device__ float g_PS[NB * 64 * MM];
// bf16 split operands, K-major: [b][n][k]
__device__ __align__(16) __nv_bfloat16 g_Ahi[NB * NN * DK];
__device__ __align__(16) __nv_bfloat16 g_Alo[NB * NN * DK];
__device__ __align__(16) __nv_bfloat16 g_Bhi[NB * MM * DK];
__device__ __align__(16) __nv_bfloat16 g_Blo[NB * MM * DK];

static __device__ __forceinline__ void cp16(uint32_t s, const void* g) {
    asm volatile("cp.async.cg.shared.global [%0], [%1], 16;\n" ::"r"(s), "l"(g));
}
#define CP_COMMIT() asm volatile("cp.async.commit_group;\n")
#define CP_WAIT1()  asm volatile("cp.async.wait_group 1;\n")
#define CP_WAIT0()  asm volatile("cp.async.wait_group 0;\n")

// ============================================================
// Transpose + bf16 split (fused: z<16 -> A, z>=16 -> B)
// ============================================================
__global__ __launch_bounds__(256) void k_conv(const float* __restrict__ EA,
                                              const float* __restrict__ EB) {
    __shared__ float tile[32][33];
    const int which = blockIdx.z >> 4;
    const int b = blockIdx.z & 15;
    const float* E = which ? EB : EA;
    __nv_bfloat16* Hi = which ? g_Bhi : g_Ahi;
    __nv_bfloat16* Lo = which ? g_Blo : g_Alo;
    const int n0 = blockIdx.x << 5;
    const int d0 = blockIdx.y << 5;
    const int tx = threadIdx.x & 31;
    const int ty = threadIdx.x >> 5;
#pragma unroll
    for (int i = ty; i < 32; i += 8)
        tile[i][tx] = E[((long)b * DK + d0 + i) * NN + n0 + tx];
    __syncthreads();
#pragma unroll
    for (int i = ty; i < 32; i += 8) {
        float x = tile[tx][i];
        __nv_bfloat16 h = __float2bfloat16(x);
        float r = x - __bfloat162float(h);
        long o = ((long)b * NN + n0 + i) * DK + d0 + tx;
        Hi[o] = h;
        Lo[o] = __float2bfloat16(r);
    }
}

// ============================================================
// mma.sync bf16x3 GEMM: 256x128 CTA tile, 8 warps of 64x64,
// BK=64, 2-stage cp.async. Higher MAC/smem-byte ratio.
// ============================================================
#define ROWP 144
#define ATILE (256 * ROWP)        // 36864
#define BTILE (128 * ROWP)        // 18432
#define STG (2 * ATILE + 2 * BTILE)  // 110592

static __device__ __forceinline__ void ldmx4(uint32_t addr, uint32_t& r0,
                                             uint32_t& r1, uint32_t& r2, uint32_t& r3) {
    asm volatile("ldmatrix.sync.aligned.m8n8.x4.shared.b16 {%0,%1,%2,%3}, [%4];"
                 : "=r"(r0), "=r"(r1), "=r"(r2), "=r"(r3) : "r"(addr));
}
static __device__ __forceinline__ void mma16816(float* c, const uint32_t* a,
                                                const uint32_t* bb) {
    asm volatile(
        "mma.sync.aligned.m16n8k16.row.col.f32.bf16.bf16.f32 "
        "{%0,%1,%2,%3}, {%4,%5,%6,%7}, {%8,%9}, {%0,%1,%2,%3};"
        : "+f"(c[0]), "+f"(c[1]), "+f"(c[2]), "+f"(c[3])
        : "r"(a[0]), "r"(a[1]), "r"(a[2]), "r"(a[3]), "r"(bb[0]), "r"(bb[1]));
}

__global__ __launch_bounds__(256, 1) void k_mma(const float* __restrict__ temp,
                                                float* __restrict__ C) {
    extern __shared__ char smem[];
    const uint32_t sb = (uint32_t)__cvta_generic_to_shared(smem);
    const int tid = threadIdx.x;
    const int wid = tid >> 5, lane = tid & 31;
    const int wr = wid >> 1;           // 0..3 : 64-row group
    const int wc = wid & 1;            // 0..1 : 64-col group
    const int b = blockIdx.z;
    const int n0 = blockIdx.y << 8;    // 256 output rows
    const int m0 = blockIdx.x << 7;    // 128 output cols

    const __nv_bfloat16* Ah = g_Ahi + ((long)b * NN + n0) * DK;
    const __nv_bfloat16* Al = g_Alo + ((long)b * NN + n0) * DK;
    const __nv_bfloat16* Bh = g_Bhi + ((long)b * MM + m0) * DK;
    const __nv_bfloat16* Bl = g_Blo + ((long)b * MM + m0) * DK;

    // one BK=64 chunk: A 2x(256 rows x 8 chunks), B 2x(128 x 8) = 6144 chunks
    auto issue = [&](int stage, int k0) {
#pragma unroll
        for (int t = tid; t < 6144; t += 256) {
            const __nv_bfloat16* gp;
            uint32_t soff;
            if (t < 4096) {
                const int tl = t >> 11;            // 0:hi 1:lo
                const int r = (t >> 3) & 255;
                const int ch = t & 7;
                gp = (tl ? Al : Ah) + (long)r * DK + k0 + ch * 8;
                soff = (uint32_t)(tl * ATILE + r * ROWP + ch * 16);
            } else {
                const int u = t - 4096;
                const int tl = u >> 10;
                const int r = (u >> 3) & 127;
                const int ch = u & 7;
                gp = (tl ? Bl : Bh) + (long)r * DK + k0 + ch * 8;
                soff = (uint32_t)(2 * ATILE + tl * BTILE + r * ROWP + ch * 16);
            }
            cp16(sb + (uint32_t)(stage * STG) + soff, gp);
        }
        CP_COMMIT();
    };

    float acc[4][8][4];
#pragma unroll
    for (int i = 0; i < 4; ++i)
#pragma unroll
        for (int j = 0; j < 8; ++j)
#pragma unroll
            for (int q = 0; q < 4; ++q) acc[i][j][q] = 0.f;

    const uint32_t aoff = (uint32_t)((lane & 15) * ROWP + ((lane >> 4) << 4));
    const int brow = (lane & 7) + ((lane >> 4) & 1) * 8;
    const uint32_t boff = (uint32_t)(brow * ROWP + (((lane >> 3) & 1) << 4));
    const int kcbase = (wid & 1) << 1;

    uint32_t afrH[4][4], afrL[4][4], bfrH[4][2], bfrL[4][2];

    auto ldA = [&](uint32_t tb, int kc, uint32_t a[4][4]) {
#pragma unroll
        for (int mt = 0; mt < 4; ++mt)
            ldmx4(tb + (uint32_t)((wr * 64 + mt * 16) * ROWP + kc * 32) + aoff,
                  a[mt][0], a[mt][1], a[mt][2], a[mt][3]);
    };
    auto ldB = [&](uint32_t tb, int kc, int nh, uint32_t bf[4][2]) {
#pragma unroll
        for (int p = 0; p < 2; ++p) {
            uint32_t r0, r1, r2, r3;
            ldmx4(tb + (uint32_t)((wc * 64 + nh * 32 + p * 16) * ROWP + kc * 32) + boff,
                  r0, r1, r2, r3);
            bf[2 * p][0] = r0; bf[2 * p][1] = r1;
            bf[2 * p + 1][0] = r2; bf[2 * p + 1][1] = r3;
        }
    };

    issue(0, 0);
    int buf = 0;
#pragma unroll 1
    for (int it = 0; it < 8; ++it) {
        if (it + 1 < 8) {
            issue(buf ^ 1, (it + 1) * 64);
            CP_WAIT1();
        } else {
            CP_WAIT0();
        }
        __syncthreads();
        const uint32_t st = sb + (uint32_t)(buf * STG);
#pragma unroll
        for (int k = 0; k < 4; ++k) {
            const int kc = (k + kcbase) & 3;
            ldA(st, kc, afrH);
            ldA(st + ATILE, kc, afrL);
#pragma unroll
            for (int nh = 0; nh < 2; ++nh) {
                ldB(st + 2 * ATILE, kc, nh, bfrH);
                ldB(st + 2 * ATILE + BTILE, kc, nh, bfrL);
#pragma unroll
                for (int mt = 0; mt < 4; ++mt)
#pragma unroll
                    for (int nt = 0; nt < 4; ++nt) {
                        float* a4 = acc[mt][nh * 4 + nt];
                        mma16816(a4, afrH[mt], bfrH[nt]);
                        mma16816(a4, afrH[mt], bfrL[nt]);
                        mma16816(a4, afrL[mt], bfrH[nt]);
                    }
            }
        }
        __syncthreads();
        buf ^= 1;
    }

    const float sc = 1.0f / (sqrtf((float)DK) * temp[b]);
    const int ib = wr * 64 + (lane >> 2);
    const int jb = wc * 64 + (lane & 3) * 2;
#pragma unroll
    for (int mt = 0; mt < 4; ++mt)
#pragma unroll
        for (int nt = 0; nt < 8; ++nt) {
            long base = (((long)(b << 10) + n0 + ib + mt * 16) << 10) + m0 + jb + nt * 8;
            *(float2*)&C[base] =
                make_float2(acc[mt][nt][0] * sc, acc[mt][nt][1] * sc);
            *(float2*)&C[base + (8 << 10)] =
                make_float2(acc[mt][nt][2] * sc, acc[mt][nt][3] * sc);
        }
}

// ============================================================
// Fused sinkhorn iteration: row-LSE (-> u) + column partials, one read.
// ============================================================
__global__ __launch_bounds__(256) void k_fused(const float* __restrict__ C, int first) {
    const int seg = blockIdx.x;   // 0..63
    const int b = blockIdx.y;     // 0..15
    const int t = threadIdx.x;    // 256
    const int wid = t >> 5, lane = t & 31;
    __shared__ float4 V4s[256];
    __shared__ float red[16][256];
    __shared__ float Ms[16];
    __shared__ float Us[16];

    V4s[t] = first ? make_float4(0.f, 0.f, 0.f, 0.f)
                   : ((const float4*)(g_V + (b << 10)))[t];
    __syncthreads();
    const float4 v4 = V4s[t];

    const float4* base = (const float4*)(C + ((long)b << 20) + ((long)seg << 14));
    float4 x[16];
#pragma unroll
    for (int i = 0; i < 16; ++i) {
        float4 c = base[(i << 8) + t];
        x[i] = make_float4(c.x + v4.x, c.y + v4.y, c.z + v4.z, c.w + v4.w);
    }

#pragma unroll
    for (int i = 0; i < 16; ++i)
        red[i][t] = fmaxf(fmaxf(x[i].x, x[i].y), fmaxf(x[i].z, x[i].w));
    __syncthreads();
#pragma unroll
    for (int rr = 0; rr < 2; ++rr) {
        const int r = 2 * wid + rr;
        float m = red[r][lane];
#pragma unroll
        for (int k = 1; k < 8; ++k) m = fmaxf(m, red[r][lane + 32 * k]);
#pragma unroll
        for (int o = 16; o; o >>= 1) m = fmaxf(m, __shfl_xor_sync(0xffffffffu, m, o));
        if (lane == 0) Ms[r] = fmaxf(m, 0.f);
    }
    __syncthreads();

    float mrow[16];
#pragma unroll
    for (int i = 0; i < 16; ++i) mrow[i] = Ms[i];
#pragma unroll
    for (int i = 0; i < 16; ++i) {
        float s = __expf(x[i].x - mrow[i]) + __expf(x[i].y - mrow[i]) +
                  __expf(x[i].z - mrow[i]) + __expf(x[i].w - mrow[i]);
        red[i][t] = s;
    }
    __syncthreads();
#pragma unroll
    for (int rr = 0; rr < 2; ++rr) {
        const int r = 2 * wid + rr;
        float s = red[r][lane];
#pragma unroll
        for (int k = 1; k < 8; ++k) s += red[r][lane + 32 * k];
#pragma unroll
        for (int o = 16; o; o >>= 1) s += __shfl_xor_sync(0xffffffffu, s, o);
        if (lane == 0) {
            float m = Ms[r];
            float u = -(m + logf(s + __expf(-m)));
            Us[r] = u;
            g_U[(b << 10) + (seg << 4) + r] = u;
        }
    }
    __syncthreads();

    float u0 = Us[0];
    float4 M = make_float4(x[0].x + u0, x[0].y + u0, x[0].z + u0, x[0].w + u0);
#pragma unroll
    for (int i = 1; i < 16; ++i) {
        float u = Us[i];
        M.x = fmaxf(M.x, x[i].x + u); M.y = fmaxf(M.y, x[i].y + u);
        M.z = fmaxf(M.z, x[i].z + u); M.w = fmaxf(M.w, x[i].w + u);
    }
    float4 S = make_float4(0.f, 0.f, 0.f, 0.f);
#pragma unroll
    for (int i = 0; i < 16; ++i) {
        float u = Us[i];
        S.x += __expf(x[i].x + u - M.x); S.y += __expf(x[i].y + u - M.y);
        S.z += __expf(x[i].z + u - M.z); S.w += __expf(x[i].w + u - M.w);
    }
    const long pidx = (((long)(b << 6) + seg) << 8) + t;
    ((float4*)g_PM)[pidx] =
        make_float4(M.x - v4.x, M.y - v4.y, M.z - v4.z, M.w - v4.w);
    ((float4*)g_PS)[pidx] = S;
}

// ============================================================
// Combine 64 segment partials per column: grid (8, NB) x 512.
// ============================================================
__global__ __launch_bounds__(512) void k_colr() {
    const int b = blockIdx.y;
    const int c = threadIdx.x & 127;
    const int q = threadIdx.x >> 7;
    const int j = (blockIdx.x << 7) + c;
    __shared__ float Msm[4][128], Ssm[4][128];

    float m[4], s[4];
#pragma unroll
    for (int t = 0; t < 4; ++t) { m[t] = -1e30f; s[t] = 0.f; }
#pragma unroll
    for (int g = 0; g < 4; ++g)
#pragma unroll
        for (int t = 0; t < 4; ++t) {
            const int sg = (q << 4) + (g << 2) + t;
            const long p = (((long)(b << 6) + sg) << 10) + j;
            float om = g_PM[p], os = g_PS[p];
            float n = fmaxf(m[t], om);
            s[t] = s[t] * __expf(m[t] - n) + os * __expf(om - n);
            m[t] = n;
        }
#pragma unroll
    for (int st = 2; st; st >>= 1)
#pragma unroll
        for (int t = 0; t < st; ++t) {
            float n = fmaxf(m[t], m[t + st]);
            s[t] = s[t] * __expf(m[t] - n) + s[t + st] * __expf(m[t + st] - n);
            m[t] = n;
        }
    Msm[q][c] = m[0];
    Ssm[q][c] = s[0];
    __syncthreads();
    if (q == 0) {
        float mm = Msm[0][c], ss = Ssm[0][c];
#pragma unroll
        for (int t = 1; t < 4; ++t) {
            float om = Msm[t][c], os = Ssm[t][c];
            float n = fmaxf(mm, om);
            ss = ss * __expf(mm - n) + os * __expf(om - n);
            mm = n;
        }
        float nn = fmaxf(mm, 0.f);
        ss = ss * __expf(mm - nn) + __expf(-nn);
        g_V[(b << 10) + j] = -(nn + logf(ss));
    }
}

// ============================================================
// Finalize
// ============================================================
__global__ __launch_bounds__(256) void k_final(float* __restrict__ C,
                                               const float* __restrict__ tgt) {
    const int gb = blockIdx.x;
    const int b = gb >> 7;
    const int row = ((gb & 127) << 3) + (threadIdx.x >> 5);
    const int lane = threadIdx.x & 31;
    __shared__ float4 Vs4[256], T04[256], T14[256], T24[256];
    const float* tb = tgt + (long)b * 3 * MM;
    Vs4[threadIdx.x] = ((const float4*)(g_V + (b << 10)))[threadIdx.x];
    T04[threadIdx.x] = ((const float4*)tb)[threadIdx.x];
    T14[threadIdx.x] = ((const float4*)(tb + MM))[threadIdx.x];
    T24[threadIdx.x] = ((const float4*)(tb + 2 * MM))[threadIdx.x];
    __syncthreads();
    float4* rp = (float4*)(C + (((long)(b << 10) + row) << 10));
    const float u = g_U[(b << 10) + row];
    float4 p[8];
    float s0 = 0.f, s1 = 0.f, s2 = 0.f, s3 = 0.f;
#pragma unroll
    for (int k = 0; k < 8; ++k) {
        float4 c = rp[lane + (k << 5)];
        float4 v = Vs4[lane + (k << 5)];
        p[k].x = __expf(c.x + u + v.x);
        p[k].y = __expf(c.y + u + v.y);
        p[k].z = __expf(c.z + u + v.z);
        p[k].w = __expf(c.w + u + v.w);
        s0 += p[k].x; s1 += p[k].y; s2 += p[k].z; s3 += p[k].w;
    }
    float sum = (s0 + s1) + (s2 + s3);
#pragma unroll
    for (int o = 16; o; o >>= 1) sum += __shfl_xor_sync(0xffffffffu, sum, o);
    const float inv = 1.f / (sum + 1e-8f);
    float w0 = 0.f, w1 = 0.f, w2 = 0.f;
#pragma unroll
    for (int k = 0; k < 8; ++k) {
        int j4 = lane + (k << 5);
        float4 pn = make_float4(p[k].x * inv, p[k].y * inv, p[k].z * inv, p[k].w * inv);
        rp[j4] = pn;
        float4 t0 = T04[j4], t1 = T14[j4], t2 = T24[j4];
        w0 = fmaf(pn.x, t0.x, fmaf(pn.y, t0.y, fmaf(pn.z, t0.z, fmaf(pn.w, t0.w, w0))));
        w1 = fmaf(pn.x, t1.x, fmaf(pn.y, t1.y, fmaf(pn.z, t1.z, fmaf(pn.w, t1.w, w1))));
        w2 = fmaf(pn.x, t2.x, fmaf(pn.y, t2.y, fmaf(pn.z, t2.z, fmaf(pn.w, t2.w, w2))));
    }
#pragma unroll
    for (int o = 16; o; o >>= 1) {
        w0 += __shfl_xor_sync(0xffffffffu, w0, o);
        w1 += __shfl_xor_sync(0xffffffffu, w1, o);
        w2 += __shfl_xor_sync(0xffffffffu, w2, o);
    }
    if (lane == 0) {
        g_W[(b << 10) + row] = sum;
        g_WT[b * 3 * NN + row] = w0;
        g_WT[b * 3 * NN + NN + row] = w1;
        g_WT[b * 3 * NN + 2 * NN + row] = w2;
    }
}

// ============================================================
// Per-batch weighted Procrustes (Horn quaternion via 4x4 Jacobi, fp64).
// ============================================================
__global__ __launch_bounds__(256) void k_proc(const float* __restrict__ src,
                                              float* __restrict__ out) {
    const int b = blockIdx.x;
    const int tid = threadIdx.x;
    __shared__ float sm[256 * 12];
    __shared__ float cent[8];
    const float* sb = src + (long)b * 3 * NN;
    const float* wb = g_W + (b << 10);
    const float* wtb = g_WT + b * 3 * NN;

    float ws = 0, s0 = 0, s1 = 0, s2 = 0, t0 = 0, t1 = 0, t2 = 0;
    for (int i = tid; i < NN; i += 256) {
        float w = wb[i];
        ws += w;
        s0 = fmaf(sb[i], w, s0);
        s1 = fmaf(sb[NN + i], w, s1);
        s2 = fmaf(sb[2 * NN + i], w, s2);
        t0 = fmaf(wtb[i], w, t0);
        t1 = fmaf(wtb[NN + i], w, t1);
        t2 = fmaf(wtb[2 * NN + i], w, t2);
    }
    sm[tid * 12 + 0] = ws; sm[tid * 12 + 1] = s0; sm[tid * 12 + 2] = s1;
    sm[tid * 12 + 3] = s2; sm[tid * 12 + 4] = t0; sm[tid * 12 + 5] = t1;
    sm[tid * 12 + 6] = t2;
    __syncthreads();
    for (int st = 128; st; st >>= 1) {
        if (tid < st)
            for (int k = 0; k < 7; ++k) sm[tid * 12 + k] += sm[(tid + st) * 12 + k];
        __syncthreads();
    }
    if (tid == 0) {
        float inv = 1.f / (sm[0] + 1e-8f);
        cent[6] = inv;
        for (int c = 0; c < 3; ++c) { cent[c] = sm[1 + c] * inv; cent[3 + c] = sm[4 + c] * inv; }
    }
    __syncthreads();
    const float inv = cent[6];
    const float sc0 = cent[0], sc1 = cent[1], sc2 = cent[2];
    const float tc0 = cent[3], tc1 = cent[4], tc2 = cent[5];

    float h[9];
#pragma unroll
    for (int k = 0; k < 9; ++k) h[k] = 0.f;
    for (int i = tid; i < NN; i += 256) {
        float wn = wb[i] * inv;
        float a0 = sb[i] - sc0, a1 = sb[NN + i] - sc1, a2 = sb[2 * NN + i] - sc2;
        float b0 = (wtb[i] - tc0) * wn;
        float b1 = (wtb[NN + i] - tc1) * wn;
        float b2 = (wtb[2 * NN + i] - tc2) * wn;
        h[0] = fmaf(a0, b0, h[0]); h[1] = fmaf(a0, b1, h[1]); h[2] = fmaf(a0, b2, h[2]);
        h[3] = fmaf(a1, b0, h[3]); h[4] = fmaf(a1, b1, h[4]); h[5] = fmaf(a1, b2, h[5]);
        h[6] = fmaf(a2, b0, h[6]); h[7] = fmaf(a2, b1, h[7]); h[8] = fmaf(a2, b2, h[8]);
    }
    __syncthreads();
    for (int k = 0; k < 9; ++k) sm[tid * 12 + k] = h[k];
    __syncthreads();
    for (int st = 128; st; st >>= 1) {
        if (tid < st)
            for (int k = 0; k < 9; ++k) sm[tid * 12 + k] += sm[(tid + st) * 12 + k];
        __syncthreads();
    }

    if (tid == 0) {
        double Sxx = sm[0], Sxy = sm[1], Sxz = sm[2];
        double Syx = sm[3], Syy = sm[4], Syz = sm[5];
        double Szx = sm[6], Szy = sm[7], Szz = sm[8];
        double A4[4][4], V4[4][4];
        A4[0][0] = Sxx + Syy + Szz;
        A4[0][1] = Syz - Szy; A4[0][2] = Szx - Sxz; A4[0][3] = Sxy - Syx;
        A4[1][1] = Sxx - Syy - Szz;
        A4[1][2] = Sxy + Syx; A4[1][3] = Szx + Sxz;
        A4[2][2] = -Sxx + Syy - Szz;
        A4[2][3] = Syz + Szy;
        A4[3][3] = -Sxx - Syy + Szz;
        A4[1][0] = A4[0][1]; A4[2][0] = A4[0][2]; A4[3][0] = A4[0][3];
        A4[2][1] = A4[1][2]; A4[3][1] = A4[1][3]; A4[3][2] = A4[2][3];
        for (int i = 0; i < 4; ++i)
            for (int j = 0; j < 4; ++j) V4[i][j] = (i == j) ? 1.0 : 0.0;
        for (int sw = 0; sw < 8; ++sw) {
            for (int p = 0; p < 3; ++p)
                for (int q = p + 1; q < 4; ++q) {
                    double apq = A4[p][q];
                    if (fabs(apq) < 1e-300) continue;
                    double tau = (A4[q][q] - A4[p][p]) / (2.0 * apq);
                    double tt = (tau >= 0 ? 1.0 : -1.0) / (fabs(tau) + sqrt(1.0 + tau * tau));
                    double cc = 1.0 / sqrt(1.0 + tt * tt);
                    double ssn = tt * cc;
                    for (int k = 0; k < 4; ++k) {
                        double r1 = A4[p][k], r2 = A4[q][k];
                        A4[p][k] = cc * r1 - ssn * r2;
                        A4[q][k] = ssn * r1 + cc * r2;
                    }
                    for (int k = 0; k < 4; ++k) {
                        double c1 = A4[k][p], c2 = A4[k][q];
                        A4[k][p] = cc * c1 - ssn * c2;
                        A4[k][q] = ssn * c1 + cc * c2;
                    }
                    for (int k = 0; k < 4; ++k) {
                        double v1 = V4[k][p], v2 = V4[k][q];
                        V4[k][p] = cc * v1 - ssn * v2;
                        V4[k][q] = ssn * v1 + cc * v2;
                    }
                }
        }
        int best = 0;
        for (int k = 1; k < 4; ++k) if (A4[k][k] > A4[best][best]) best = k;
        double q0 = V4[0][best], qx = V4[1][best], qy = V4[2][best], qz = V4[3][best];
        double qn = 1.0 / sqrt(q0 * q0 + qx * qx + qy * qy + qz * qz);
        q0 *= qn; qx *= qn; qy *= qn; qz *= qn;
        double R_[3][3];
        R_[0][0] = 1 - 2 * (qy * qy + qz * qz);
        R_[0][1] = 2 * (qx * qy - q0 * qz);
        R_[0][2] = 2 * (qx * qz + q0 * qy);
        R_[1][0] = 2 * (qx * qy + q0 * qz);
        R_[1][1] = 1 - 2 * (qx * qx + qz * qz);
        R_[1][2] = 2 * (qy * qz - q0 * qx);
        R_[2][0] = 2 * (qx * qz - q0 * qy);
        R_[2][1] = 2 * (qy * qz + q0 * qx);
        R_[2][2] = 1 - 2 * (qx * qx + qy * qy);
        double H_[3][3] = {{Sxx, Sxy, Sxz}, {Syx, Syy, Syz}, {Szx, Szy, Szz}};
        double tr1 = 0, tr2 = 0;
        for (int i = 0; i < 3; ++i)
            for (int k = 0; k < 3; ++k) {
                tr1 += R_[i][k] * H_[k][i];
                tr2 += R_[k][i] * H_[k][i];
            }
        if (tr2 > tr1) {
            for (int i = 0; i < 3; ++i)
                for (int k = i + 1; k < 3; ++k) {
                    double tmp = R_[i][k]; R_[i][k] = R_[k][i]; R_[k][i] = tmp;
                }
        }
        double scv[3] = {sc0, sc1, sc2}, tcv[3] = {tc0, tc1, tc2};
        for (int i = 0; i < 3; ++i)
            for (int k = 0; k < 3; ++k)
                out[b * 9 + i * 3 + k] = (float)R_[i][k];
        for (int c = 0; c < 3; ++c) {
            double tv = tcv[c];
            for (int k = 0; k < 3; ++k) tv -= R_[c][k] * scv[k];
            out[NB * 9 + b * 3 + c] = (float)tv;
        }
    }
}

// ============================================================
extern "C" void kernel_launch(void* const* d_in, const int* in_sizes, int n_in,
                              void* d_out, int out_size) {
    const float* srcE = (const float*)d_in[0];
    const float* tgtE = (const float*)d_in[1];
    const float* src  = (const float*)d_in[2];
    const float* tgt  = (const float*)d_in[3];
    const float* temp = (const float*)d_in[4];
    float* out = (float*)d_out;
    float* aff = out + NB * 9 + NB * 3;

    (void)in_sizes; (void)n_in; (void)out_size;

    const int SMEM_SZ = 2 * STG;   // 221184
    static int configured = 0;
    if (!configured) {
        cudaFuncSetAttribute(k_mma, cudaFuncAttributeMaxDynamicSharedMemorySize, SMEM_SZ);
        configured = 1;
    }

    k_conv<<<dim3(32, 16, 32), 256>>>(srcE, tgtE);
    k_mma<<<dim3(8, 4, NB), 256, SMEM_SZ>>>(temp, aff);
    for (int it = 0; it < 5; ++it) {
        k_fused<<<dim3(64, NB), 256>>>(aff, it == 0);
        k_colr<<<dim3(8, NB), 512>>>();
    }
    k_final<<<2048, 256>>>(aff, tgt);
    k_proc<<<NB, 256>>>(src, out);
}

// round 11
// speedup vs baseline: 1.0146x; 1.0146x over previous
#include <cuda_runtime.h>
#include <cuda_bf16.h>
#include <math.h>
#include <stdint.h>

#define NB 16
#define NN 1024
#define MM 1024
#define DK 512

// -------- device scratch (no allocations allowed) --------
__device__ float g_U[NB * NN];
__device__ float g_V[NB * MM];
__device__ float g_W[NB * NN];
__device__ float g_WT[NB * 3 * NN];
__device__ float g_PM[NB * 64 * MM];
__device__ float g_PS[NB * 64 * MM];
// bf16 split operands, K-major: [b][n][k]
__device__ __align__(16) __nv_bfloat16 g_Ahi[NB * NN * DK];
__device__ __align__(16) __nv_bfloat16 g_Alo[NB * NN * DK];
__device__ __align__(16) __nv_bfloat16 g_Bhi[NB * MM * DK];
__device__ __align__(16) __nv_bfloat16 g_Blo[NB * MM * DK];

static __device__ __forceinline__ void cp16(uint32_t s, const void* g) {
    asm volatile("cp.async.cg.shared.global [%0], [%1], 16;\n" ::"r"(s), "l"(g));
}
#define CP_COMMIT() asm volatile("cp.async.commit_group;\n")
#define CP_WAIT1()  asm volatile("cp.async.wait_group 1;\n")
#define CP_WAIT0()  asm volatile("cp.async.wait_group 0;\n")

// ============================================================
// Transpose + bf16 split, packed uint32 stores (2 bf16 along d).
// ============================================================
__global__ __launch_bounds__(256) void k_conv(const float* __restrict__ EA,
                                              const float* __restrict__ EB) {
    __shared__ float tile[32][33];
    const int which = blockIdx.z >> 4;
    const int b = blockIdx.z & 15;
    const float* E = which ? EB : EA;
    __nv_bfloat16* Hi = which ? g_Bhi : g_Ahi;
    __nv_bfloat16* Lo = which ? g_Blo : g_Alo;
    const int n0 = blockIdx.x << 5;
    const int d0 = blockIdx.y << 5;
    const int tx = threadIdx.x & 31;
    const int ty = threadIdx.x >> 5;
#pragma unroll
    for (int i = ty; i < 32; i += 8)
        tile[i][tx] = E[((long)b * DK + d0 + i) * NN + n0 + tx];
    __syncthreads();
#pragma unroll
    for (int it = threadIdx.x; it < 512; it += 256) {
        const int n = it >> 4;       // 0..31
        const int dp = it & 15;      // 0..15 (d pair)
        float x0 = tile[2 * dp][n];
        float x1 = tile[2 * dp + 1][n];
        __nv_bfloat16 h0 = __float2bfloat16(x0);
        __nv_bfloat16 h1 = __float2bfloat16(x1);
        float r0 = x0 - __bfloat162float(h0);
        float r1 = x1 - __bfloat162float(h1);
        __nv_bfloat16 l0 = __float2bfloat16(r0);
        __nv_bfloat16 l1 = __float2bfloat16(r1);
        long o = ((long)b * NN + n0 + n) * DK + d0 + 2 * dp;
        uint32_t hp, lp;
        {
            uint16_t a, bb;
            memcpy(&a, &h0, 2); memcpy(&bb, &h1, 2);
            hp = (uint32_t)a | ((uint32_t)bb << 16);
            memcpy(&a, &l0, 2); memcpy(&bb, &l1, 2);
            lp = (uint32_t)a | ((uint32_t)bb << 16);
        }
        *(uint32_t*)&Hi[o] = hp;
        *(uint32_t*)&Lo[o] = lp;
    }
}

// ============================================================
// mma.sync bf16x3 GEMM: 128x128 CTA tile, 2x4 warp grid, 64x32 warp tile,
// BK=64, 3-stage cp.async, one sync per BK, warp-parity kc stagger.
// (round-9 config — best measured)
// ============================================================
#define ROWP 144
#define TILE_B (128 * ROWP)
#define STAGE_B (4 * TILE_B)

static __device__ __forceinline__ void ldmx4(uint32_t addr, uint32_t& r0,
                                             uint32_t& r1, uint32_t& r2, uint32_t& r3) {
    asm volatile("ldmatrix.sync.aligned.m8n8.x4.shared.b16 {%0,%1,%2,%3}, [%4];"
                 : "=r"(r0), "=r"(r1), "=r"(r2), "=r"(r3) : "r"(addr));
}
static __device__ __forceinline__ void mma16816(float* c, const uint32_t* a,
                                                const uint32_t* bb) {
    asm volatile(
        "mma.sync.aligned.m16n8k16.row.col.f32.bf16.bf16.f32 "
        "{%0,%1,%2,%3}, {%4,%5,%6,%7}, {%8,%9}, {%0,%1,%2,%3};"
        : "+f"(c[0]), "+f"(c[1]), "+f"(c[2]), "+f"(c[3])
        : "r"(a[0]), "r"(a[1]), "r"(a[2]), "r"(a[3]), "r"(bb[0]), "r"(bb[1]));
}

__global__ __launch_bounds__(256, 1) void k_mma(const float* __restrict__ temp,
                                                float* __restrict__ C) {
    extern __shared__ char smem[];
    const uint32_t sb = (uint32_t)__cvta_generic_to_shared(smem);
    const int tid = threadIdx.x;
    const int wid = tid >> 5, lane = tid & 31;
    const int wr = wid >> 2;
    const int wc = wid & 3;
    const int b = blockIdx.z;
    const int n0 = blockIdx.y << 7;
    const int m0 = blockIdx.x << 7;

    const __nv_bfloat16* Ah = g_Ahi + ((long)b * NN + n0) * DK;
    const __nv_bfloat16* Al = g_Alo + ((long)b * NN + n0) * DK;
    const __nv_bfloat16* Bh = g_Bhi + ((long)b * MM + m0) * DK;
    const __nv_bfloat16* Bl = g_Blo + ((long)b * MM + m0) * DK;

    auto issue = [&](int stage, int k0) {
#pragma unroll
        for (int t = tid; t < 4096; t += 256) {
            const int tile = t >> 10;
            const int row = (t >> 3) & 127;
            const int ch = t & 7;
            const __nv_bfloat16* g =
                (tile == 0 ? Ah : tile == 1 ? Al : tile == 2 ? Bh : Bl) +
                (long)row * DK + k0 + ch * 8;
            cp16(sb + (uint32_t)(stage * STAGE_B + tile * TILE_B + row * ROWP + ch * 16), g);
        }
        CP_COMMIT();
    };

    float acc[4][4][4];
#pragma unroll
    for (int i = 0; i < 4; ++i)
#pragma unroll
        for (int j = 0; j < 4; ++j)
#pragma unroll
            for (int q = 0; q < 4; ++q) acc[i][j][q] = 0.f;

    const uint32_t aoff = (uint32_t)((lane & 15) * ROWP + ((lane >> 4) << 4));
    const int brow = (lane & 7) + ((lane >> 4) & 1) * 8;
    const uint32_t boff = (uint32_t)(brow * ROWP + (((lane >> 3) & 1) << 4));
    const int kcbase = (wid & 1) << 1;

    uint32_t afrH[4][4], afrL[4][4], bfrH[4][2], bfrL[4][2];

    auto ldA = [&](uint32_t tb, int kc, uint32_t a[4][4]) {
#pragma unroll
        for (int mt = 0; mt < 4; ++mt)
            ldmx4(tb + (uint32_t)((wr * 64 + mt * 16) * ROWP + kc * 32) + aoff,
                  a[mt][0], a[mt][1], a[mt][2], a[mt][3]);
    };
    auto ldB = [&](uint32_t tb, int kc, uint32_t bf[4][2]) {
#pragma unroll
        for (int p = 0; p < 2; ++p) {
            uint32_t r0, r1, r2, r3;
            ldmx4(tb + (uint32_t)((wc * 32 + p * 16) * ROWP + kc * 32) + boff,
                  r0, r1, r2, r3);
            bf[2 * p][0] = r0; bf[2 * p][1] = r1;
            bf[2 * p + 1][0] = r2; bf[2 * p + 1][1] = r3;
        }
    };
    auto domma = [&](uint32_t a[4][4], uint32_t bf[4][2]) {
#pragma unroll
        for (int mt = 0; mt < 4; ++mt)
#pragma unroll
            for (int nt = 0; nt < 4; ++nt)
                mma16816(acc[mt][nt], a[mt], bf[nt]);
    };

    issue(0, 0);
    issue(1, 64);
#pragma unroll 1
    for (int it = 0; it < 8; ++it) {
        if (it + 1 < 8) CP_WAIT1(); else CP_WAIT0();
        __syncthreads();
        if (it + 2 < 8) issue((it + 2) % 3, (it + 2) * 64);
        const uint32_t st = sb + (uint32_t)((it % 3) * STAGE_B);
#pragma unroll
        for (int k = 0; k < 4; ++k) {
            const int kc = (k + kcbase) & 3;
            ldA(st, kc, afrH);
            ldA(st + TILE_B, kc, afrL);
            ldB(st + 2 * TILE_B, kc, bfrH);
            ldB(st + 3 * TILE_B, kc, bfrL);
            domma(afrH, bfrH);
            domma(afrH, bfrL);
            domma(afrL, bfrH);
        }
    }

    const float sc = 1.0f / (sqrtf((float)DK) * temp[b]);
    const int ib = wr * 64 + (lane >> 2);
    const int jb = wc * 32 + (lane & 3) * 2;
#pragma unroll
    for (int mt = 0; mt < 4; ++mt)
#pragma unroll
        for (int nt = 0; nt < 4; ++nt) {
            long base = (((long)(b << 10) + n0 + ib + mt * 16) << 10) + m0 + jb + nt * 8;
            *(float2*)&C[base] =
                make_float2(acc[mt][nt][0] * sc, acc[mt][nt][1] * sc);
            *(float2*)&C[base + (8 << 10)] =
                make_float2(acc[mt][nt][2] * sc, acc[mt][nt][3] * sc);
        }
}

// ============================================================
// Fused sinkhorn iteration: row-LSE (-> u) + column partials, one read.
// ============================================================
__global__ __launch_bounds__(256) void k_fused(const float* __restrict__ C, int first) {
    const int seg = blockIdx.x;   // 0..63
    const int b = blockIdx.y;     // 0..15
    const int t = threadIdx.x;    // 256
    const int wid = t >> 5, lane = t & 31;
    __shared__ float4 V4s[256];
    __shared__ float red[16][256];
    __shared__ float Ms[16];
    __shared__ float Us[16];

    V4s[t] = first ? make_float4(0.f, 0.f, 0.f, 0.f)
                   : ((const float4*)(g_V + (b << 10)))[t];
    __syncthreads();
    const float4 v4 = V4s[t];

    const float4* base = (const float4*)(C + ((long)b << 20) + ((long)seg << 14));
    float4 x[16];
#pragma unroll
    for (int i = 0; i < 16; ++i) {
        float4 c = base[(i << 8) + t];
        x[i] = make_float4(c.x + v4.x, c.y + v4.y, c.z + v4.z, c.w + v4.w);
    }

#pragma unroll
    for (int i = 0; i < 16; ++i)
        red[i][t] = fmaxf(fmaxf(x[i].x, x[i].y), fmaxf(x[i].z, x[i].w));
    __syncthreads();
#pragma unroll
    for (int rr = 0; rr < 2; ++rr) {
        const int r = 2 * wid + rr;
        float m = red[r][lane];
#pragma unroll
        for (int k = 1; k < 8; ++k) m = fmaxf(m, red[r][lane + 32 * k]);
#pragma unroll
        for (int o = 16; o; o >>= 1) m = fmaxf(m, __shfl_xor_sync(0xffffffffu, m, o));
        if (lane == 0) Ms[r] = fmaxf(m, 0.f);
    }
    __syncthreads();

    float mrow[16];
#pragma unroll
    for (int i = 0; i < 16; ++i) mrow[i] = Ms[i];
#pragma unroll
    for (int i = 0; i < 16; ++i) {
        float s = __expf(x[i].x - mrow[i]) + __expf(x[i].y - mrow[i]) +
                  __expf(x[i].z - mrow[i]) + __expf(x[i].w - mrow[i]);
        red[i][t] = s;
    }
    __syncthreads();
#pragma unroll
    for (int rr = 0; rr < 2; ++rr) {
        const int r = 2 * wid + rr;
        float s = red[r][lane];
#pragma unroll
        for (int k = 1; k < 8; ++k) s += red[r][lane + 32 * k];
#pragma unroll
        for (int o = 16; o; o >>= 1) s += __shfl_xor_sync(0xffffffffu, s, o);
        if (lane == 0) {
            float m = Ms[r];
            float u = -(m + logf(s + __expf(-m)));
            Us[r] = u;
            g_U[(b << 10) + (seg << 4) + r] = u;
        }
    }
    __syncthreads();

    float u0 = Us[0];
    float4 M = make_float4(x[0].x + u0, x[0].y + u0, x[0].z + u0, x[0].w + u0);
#pragma unroll
    for (int i = 1; i < 16; ++i) {
        float u = Us[i];
        M.x = fmaxf(M.x, x[i].x + u); M.y = fmaxf(M.y, x[i].y + u);
        M.z = fmaxf(M.z, x[i].z + u); M.w = fmaxf(M.w, x[i].w + u);
    }
    float4 S = make_float4(0.f, 0.f, 0.f, 0.f);
#pragma unroll
    for (int i = 0; i < 16; ++i) {
        float u = Us[i];
        S.x += __expf(x[i].x + u - M.x); S.y += __expf(x[i].y + u - M.y);
        S.z += __expf(x[i].z + u - M.z); S.w += __expf(x[i].w + u - M.w);
    }
    const long pidx = (((long)(b << 6) + seg) << 8) + t;
    ((float4*)g_PM)[pidx] =
        make_float4(M.x - v4.x, M.y - v4.y, M.z - v4.z, M.w - v4.w);
    ((float4*)g_PS)[pidx] = S;
}

// ============================================================
// Combine 64 segment partials per column: grid (32, NB) x 256.
// 8 threads/column, each folds 8 segments (2 chains of 4).
// ============================================================
__global__ __launch_bounds__(256) void k_colr() {
    const int b = blockIdx.y;
    const int c = threadIdx.x & 31;
    const int q = threadIdx.x >> 5;          // 0..7
    const int j = (blockIdx.x << 5) + c;
    __shared__ float Msm[8][32], Ssm[8][32];

    float m[2] = {-1e30f, -1e30f}, s[2] = {0.f, 0.f};
#pragma unroll
    for (int g = 0; g < 4; ++g)
#pragma unroll
        for (int t = 0; t < 2; ++t) {
            const int sg = (q << 3) + (g << 1) + t;
            const long p = (((long)(b << 6) + sg) << 10) + j;
            float om = g_PM[p], os = g_PS[p];
            float n = fmaxf(m[t], om);
            s[t] = s[t] * __expf(m[t] - n) + os * __expf(om - n);
            m[t] = n;
        }
    {
        float n = fmaxf(m[0], m[1]);
        s[0] = s[0] * __expf(m[0] - n) + s[1] * __expf(m[1] - n);
        m[0] = n;
    }
    Msm[q][c] = m[0];
    Ssm[q][c] = s[0];
    __syncthreads();
    if (q == 0) {
        float mm = Msm[0][c], ss = Ssm[0][c];
#pragma unroll
        for (int t = 1; t < 8; ++t) {
            float om = Msm[t][c], os = Ssm[t][c];
            float n = fmaxf(mm, om);
            ss = ss * __expf(mm - n) + os * __expf(om - n);
            mm = n;
        }
        float nn = fmaxf(mm, 0.f);
        ss = ss * __expf(mm - nn) + __expf(-nn);
        g_V[(b << 10) + j] = -(nn + logf(ss));
    }
}

// ============================================================
// Finalize
// ============================================================
__global__ __launch_bounds__(256) void k_final(float* __restrict__ C,
                                               const float* __restrict__ tgt) {
    const int gb = blockIdx.x;
    const int b = gb >> 7;
    const int row = ((gb & 127) << 3) + (threadIdx.x >> 5);
    const int lane = threadIdx.x & 31;
    __shared__ float4 Vs4[256], T04[256], T14[256], T24[256];
    const float* tb = tgt + (long)b * 3 * MM;
    Vs4[threadIdx.x] = ((const float4*)(g_V + (b << 10)))[threadIdx.x];
    T04[threadIdx.x] = ((const float4*)tb)[threadIdx.x];
    T14[threadIdx.x] = ((const float4*)(tb + MM))[threadIdx.x];
    T24[threadIdx.x] = ((const float4*)(tb + 2 * MM))[threadIdx.x];
    __syncthreads();
    float4* rp = (float4*)(C + (((long)(b << 10) + row) << 10));
    const float u = g_U[(b << 10) + row];
    float4 p[8];
    float s0 = 0.f, s1 = 0.f, s2 = 0.f, s3 = 0.f;
#pragma unroll
    for (int k = 0; k < 8; ++k) {
        float4 c = rp[lane + (k << 5)];
        float4 v = Vs4[lane + (k << 5)];
        p[k].x = __expf(c.x + u + v.x);
        p[k].y = __expf(c.y + u + v.y);
        p[k].z = __expf(c.z + u + v.z);
        p[k].w = __expf(c.w + u + v.w);
        s0 += p[k].x; s1 += p[k].y; s2 += p[k].z; s3 += p[k].w;
    }
    float sum = (s0 + s1) + (s2 + s3);
#pragma unroll
    for (int o = 16; o; o >>= 1) sum += __shfl_xor_sync(0xffffffffu, sum, o);
    const float inv = 1.f / (sum + 1e-8f);
    float w0 = 0.f, w1 = 0.f, w2 = 0.f;
#pragma unroll
    for (int k = 0; k < 8; ++k) {
        int j4 = lane + (k << 5);
        float4 pn = make_float4(p[k].x * inv, p[k].y * inv, p[k].z * inv, p[k].w * inv);
        rp[j4] = pn;
        float4 t0 = T04[j4], t1 = T14[j4], t2 = T24[j4];
        w0 = fmaf(pn.x, t0.x, fmaf(pn.y, t0.y, fmaf(pn.z, t0.z, fmaf(pn.w, t0.w, w0))));
        w1 = fmaf(pn.x, t1.x, fmaf(pn.y, t1.y, fmaf(pn.z, t1.z, fmaf(pn.w, t1.w, w1))));
        w2 = fmaf(pn.x, t2.x, fmaf(pn.y, t2.y, fmaf(pn.z, t2.z, fmaf(pn.w, t2.w, w2))));
    }
#pragma unroll
    for (int o = 16; o; o >>= 1) {
        w0 += __shfl_xor_sync(0xffffffffu, w0, o);
        w1 += __shfl_xor_sync(0xffffffffu, w1, o);
        w2 += __shfl_xor_sync(0xffffffffu, w2, o);
    }
    if (lane == 0) {
        g_W[(b << 10) + row] = sum;
        g_WT[b * 3 * NN + row] = w0;
        g_WT[b * 3 * NN + NN + row] = w1;
        g_WT[b * 3 * NN + 2 * NN + row] = w2;
    }
}

// ============================================================
// Per-batch weighted Procrustes (Horn quaternion via 4x4 Jacobi, fp64).
// ============================================================
__global__ __launch_bounds__(256) void k_proc(const float* __restrict__ src,
                                              float* __restrict__ out) {
    const int b = blockIdx.x;
    const int tid = threadIdx.x;
    __shared__ float sm[256 * 12];
    __shared__ float cent[8];
    const float* sb = src + (long)b * 3 * NN;
    const float* wb = g_W + (b << 10);
    const float* wtb = g_WT + b * 3 * NN;

    float ws = 0, s0 = 0, s1 = 0, s2 = 0, t0 = 0, t1 = 0, t2 = 0;
    for (int i = tid; i < NN; i += 256) {
        float w = wb[i];
        ws += w;
        s0 = fmaf(sb[i], w, s0);
        s1 = fmaf(sb[NN + i], w, s1);
        s2 = fmaf(sb[2 * NN + i], w, s2);
        t0 = fmaf(wtb[i], w, t0);
        t1 = fmaf(wtb[NN + i], w, t1);
        t2 = fmaf(wtb[2 * NN + i], w, t2);
    }
    sm[tid * 12 + 0] = ws; sm[tid * 12 + 1] = s0; sm[tid * 12 + 2] = s1;
    sm[tid * 12 + 3] = s2; sm[tid * 12 + 4] = t0; sm[tid * 12 + 5] = t1;
    sm[tid * 12 + 6] = t2;
    __syncthreads();
    for (int st = 128; st; st >>= 1) {
        if (tid < st)
            for (int k = 0; k < 7; ++k) sm[tid * 12 + k] += sm[(tid + st) * 12 + k];
        __syncthreads();
    }
    if (tid == 0) {
        float inv = 1.f / (sm[0] + 1e-8f);
        cent[6] = inv;
        for (int c = 0; c < 3; ++c) { cent[c] = sm[1 + c] * inv; cent[3 + c] = sm[4 + c] * inv; }
    }
    __syncthreads();
    const float inv = cent[6];
    const float sc0 = cent[0], sc1 = cent[1], sc2 = cent[2];
    const float tc0 = cent[3], tc1 = cent[4], tc2 = cent[5];

    float h[9];
#pragma unroll
    for (int k = 0; k < 9; ++k) h[k] = 0.f;
    for (int i = tid; i < NN; i += 256) {
        float wn = wb[i] * inv;
        float a0 = sb[i] - sc0, a1 = sb[NN + i] - sc1, a2 = sb[2 * NN + i] - sc2;
        float b0 = (wtb[i] - tc0) * wn;
        float b1 = (wtb[NN + i] - tc1) * wn;
        float b2 = (wtb[2 * NN + i] - tc2) * wn;
        h[0] = fmaf(a0, b0, h[0]); h[1] = fmaf(a0, b1, h[1]); h[2] = fmaf(a0, b2, h[2]);
        h[3] = fmaf(a1, b0, h[3]); h[4] = fmaf(a1, b1, h[4]); h[5] = fmaf(a1, b2, h[5]);
        h[6] = fmaf(a2, b0, h[6]); h[7] = fmaf(a2, b1, h[7]); h[8] = fmaf(a2, b2, h[8]);
    }
    __syncthreads();
    for (int k = 0; k < 9; ++k) sm[tid * 12 + k] = h[k];
    __syncthreads();
    for (int st = 128; st; st >>= 1) {
        if (tid < st)
            for (int k = 0; k < 9; ++k) sm[tid * 12 + k] += sm[(tid + st) * 12 + k];
        __syncthreads();
    }

    if (tid == 0) {
        double Sxx = sm[0], Sxy = sm[1], Sxz = sm[2];
        double Syx = sm[3], Syy = sm[4], Syz = sm[5];
        double Szx = sm[6], Szy = sm[7], Szz = sm[8];
        double A4[4][4], V4[4][4];
        A4[0][0] = Sxx + Syy + Szz;
        A4[0][1] = Syz - Szy; A4[0][2] = Szx - Sxz; A4[0][3] = Sxy - Syx;
        A4[1][1] = Sxx - Syy - Szz;
        A4[1][2] = Sxy + Syx; A4[1][3] = Szx + Sxz;
        A4[2][2] = -Sxx + Syy - Szz;
        A4[2][3] = Syz + Szy;
        A4[3][3] = -Sxx - Syy + Szz;
        A4[1][0] = A4[0][1]; A4[2][0] = A4[0][2]; A4[3][0] = A4[0][3];
        A4[2][1] = A4[1][2]; A4[3][1] = A4[1][3]; A4[3][2] = A4[2][3];
        for (int i = 0; i < 4; ++i)
            for (int j = 0; j < 4; ++j) V4[i][j] = (i == j) ? 1.0 : 0.0;
        for (int sw = 0; sw < 8; ++sw) {
            for (int p = 0; p < 3; ++p)
                for (int q = p + 1; q < 4; ++q) {
                    double apq = A4[p][q];
                    if (fabs(apq) < 1e-300) continue;
                    double tau = (A4[q][q] - A4[p][p]) / (2.0 * apq);
                    double tt = (tau >= 0 ? 1.0 : -1.0) / (fabs(tau) + sqrt(1.0 + tau * tau));
                    double cc = 1.0 / sqrt(1.0 + tt * tt);
                    double ssn = tt * cc;
                    for (int k = 0; k < 4; ++k) {
                        double r1 = A4[p][k], r2 = A4[q][k];
                        A4[p][k] = cc * r1 - ssn * r2;
                        A4[q][k] = ssn * r1 + cc * r2;
                    }
                    for (int k = 0; k < 4; ++k) {
                        double c1 = A4[k][p], c2 = A4[k][q];
                        A4[k][p] = cc * c1 - ssn * c2;
                        A4[k][q] = ssn * c1 + cc * c2;
                    }
                    for (int k = 0; k < 4; ++k) {
                        double v1 = V4[k][p], v2 = V4[k][q];
                        V4[k][p] = cc * v1 - ssn * v2;
                        V4[k][q] = ssn * v1 + cc * v2;
                    }
                }
        }
        int best = 0;
        for (int k = 1; k < 4; ++k) if (A4[k][k] > A4[best][best]) best = k;
        double q0 = V4[0][best], qx = V4[1][best], qy = V4[2][best], qz = V4[3][best];
        double qn = 1.0 / sqrt(q0 * q0 + qx * qx + qy * qy + qz * qz);
        q0 *= qn; qx *= qn; qy *= qn; qz *= qn;
        double R_[3][3];
        R_[0][0] = 1 - 2 * (qy * qy + qz * qz);
        R_[0][1] = 2 * (qx * qy - q0 * qz);
        R_[0][2] = 2 * (qx * qz + q0 * qy);
        R_[1][0] = 2 * (qx * qy + q0 * qz);
        R_[1][1] = 1 - 2 * (qx * qx + qz * qz);
        R_[1][2] = 2 * (qy * qz - q0 * qx);
        R_[2][0] = 2 * (qx * qz - q0 * qy);
        R_[2][1] = 2 * (qy * qz + q0 * qx);
        R_[2][2] = 1 - 2 * (qx * qx + qy * qy);
        double H_[3][3] = {{Sxx, Sxy, Sxz}, {Syx, Syy, Syz}, {Szx, Szy, Szz}};
        double tr1 = 0, tr2 = 0;
        for (int i = 0; i < 3; ++i)
            for (int k = 0; k < 3; ++k) {
                tr1 += R_[i][k] * H_[k][i];
                tr2 += R_[k][i] * H_[k][i];
            }
        if (tr2 > tr1) {
            for (int i = 0; i < 3; ++i)
                for (int k = i + 1; k < 3; ++k) {
                    double tmp = R_[i][k]; R_[i][k] = R_[k][i]; R_[k][i] = tmp;
                }
        }
        double scv[3] = {sc0, sc1, sc2}, tcv[3] = {tc0, tc1, tc2};
        for (int i = 0; i < 3; ++i)
            for (int k = 0; k < 3; ++k)
                out[b * 9 + i * 3 + k] = (float)R_[i][k];
        for (int c = 0; c < 3; ++c) {
            double tv = tcv[c];
            for (int k = 0; k < 3; ++k) tv -= R_[c][k] * scv[k];
            out[NB * 9 + b * 3 + c] = (float)tv;
        }
    }
}

// ============================================================
extern "C" void kernel_launch(void* const* d_in, const int* in_sizes, int n_in,
                              void* d_out, int out_size) {
    const float* srcE = (const float*)d_in[0];
    const float* tgtE = (const float*)d_in[1];
    const float* src  = (const float*)d_in[2];
    const float* tgt  = (const float*)d_in[3];
    const float* temp = (const float*)d_in[4];
    float* out = (float*)d_out;
    float* aff = out + NB * 9 + NB * 3;

    (void)in_sizes; (void)n_in; (void)out_size;

    const int SMEM_SZ = 3 * STAGE_B;   // 221184
    static int configured = 0;
    if (!configured) {
        cudaFuncSetAttribute(k_mma, cudaFuncAttributeMaxDynamicSharedMemorySize, SMEM_SZ);
        configured = 1;
    }

    k_conv<<<dim3(32, 16, 32), 256>>>(srcE, tgtE);
    k_mma<<<dim3(8, 8, NB), 256, SMEM_SZ>>>(temp, aff);
    for (int it = 0; it < 5; ++it) {
        k_fused<<<dim3(64, NB), 256>>>(aff, it == 0);
        k_colr<<<dim3(32, NB), 256>>>();
    }
    k_final<<<2048, 256>>>(aff, tgt);
    k_proc<<<NB, 256>>>(src, out);
}

// round 12
// speedup vs baseline: 1.0284x; 1.0136x over previous
#include <cuda_runtime.h>
#include <cuda_bf16.h>
#include <math.h>
#include <stdint.h>

#define NB 16
#define NN 1024
#define MM 1024
#define DK 512

// -------- device scratch (no allocations allowed) --------
__device__ float g_U[NB * NN];
__device__ float g_V[NB * MM];
__device__ float g_W[NB * NN];
__device__ float g_WT[NB * 3 * NN];
__device__ float g_PM[NB * 64 * MM];
__device__ float g_PS[NB * 64 * MM];
// bf16 split operands, K-major: [b][n][k]
__device__ __align__(16) __nv_bfloat16 g_Ahi[NB * NN * DK];
__device__ __align__(16) __nv_bfloat16 g_Alo[NB * NN * DK];
__device__ __align__(16) __nv_bfloat16 g_Bhi[NB * MM * DK];
__device__ __align__(16) __nv_bfloat16 g_Blo[NB * MM * DK];

static __device__ __forceinline__ void cp16(uint32_t s, const void* g) {
    asm volatile("cp.async.cg.shared.global [%0], [%1], 16;\n" ::"r"(s), "l"(g));
}
#define CP_COMMIT() asm volatile("cp.async.commit_group;\n")
#define CP_WAIT1()  asm volatile("cp.async.wait_group 1;\n")
#define CP_WAIT0()  asm volatile("cp.async.wait_group 0;\n")

// ============================================================
// Transpose + bf16 split, packed uint32 stores.
// ============================================================
__global__ __launch_bounds__(256) void k_conv(const float* __restrict__ EA,
                                              const float* __restrict__ EB) {
    __shared__ float tile[32][33];
    const int which = blockIdx.z >> 4;
    const int b = blockIdx.z & 15;
    const float* E = which ? EB : EA;
    __nv_bfloat16* Hi = which ? g_Bhi : g_Ahi;
    __nv_bfloat16* Lo = which ? g_Blo : g_Alo;
    const int n0 = blockIdx.x << 5;
    const int d0 = blockIdx.y << 5;
    const int tx = threadIdx.x & 31;
    const int ty = threadIdx.x >> 5;
#pragma unroll
    for (int i = ty; i < 32; i += 8)
        tile[i][tx] = E[((long)b * DK + d0 + i) * NN + n0 + tx];
    __syncthreads();
#pragma unroll
    for (int it = threadIdx.x; it < 512; it += 256) {
        const int n = it >> 4;
        const int dp = it & 15;
        float x0 = tile[2 * dp][n];
        float x1 = tile[2 * dp + 1][n];
        __nv_bfloat16 h0 = __float2bfloat16(x0);
        __nv_bfloat16 h1 = __float2bfloat16(x1);
        float r0 = x0 - __bfloat162float(h0);
        float r1 = x1 - __bfloat162float(h1);
        __nv_bfloat16 l0 = __float2bfloat16(r0);
        __nv_bfloat16 l1 = __float2bfloat16(r1);
        long o = ((long)b * NN + n0 + n) * DK + d0 + 2 * dp;
        uint32_t hp, lp;
        {
            uint16_t a, bb;
            memcpy(&a, &h0, 2); memcpy(&bb, &h1, 2);
            hp = (uint32_t)a | ((uint32_t)bb << 16);
            memcpy(&a, &l0, 2); memcpy(&bb, &l1, 2);
            lp = (uint32_t)a | ((uint32_t)bb << 16);
        }
        *(uint32_t*)&Hi[o] = hp;
        *(uint32_t*)&Lo[o] = lp;
    }
}

// ============================================================
// mma.sync bf16x3 GEMM: 128x128 CTA tile, 2x4 warps, 64x32 warp tile,
// BK=32, 2-stage double buffer, 2 CTAs/SM (regs capped), A-frag reuse.
// ============================================================
#define ROWP2 80
#define TIL2 (128 * ROWP2)        // 10240
#define STG2 (4 * TIL2)           // 40960

static __device__ __forceinline__ void ldmx4(uint32_t addr, uint32_t& r0,
                                             uint32_t& r1, uint32_t& r2, uint32_t& r3) {
    asm volatile("ldmatrix.sync.aligned.m8n8.x4.shared.b16 {%0,%1,%2,%3}, [%4];"
                 : "=r"(r0), "=r"(r1), "=r"(r2), "=r"(r3) : "r"(addr));
}
static __device__ __forceinline__ void mma16816(float* c, const uint32_t* a,
                                                const uint32_t* bb) {
    asm volatile(
        "mma.sync.aligned.m16n8k16.row.col.f32.bf16.bf16.f32 "
        "{%0,%1,%2,%3}, {%4,%5,%6,%7}, {%8,%9}, {%0,%1,%2,%3};"
        : "+f"(c[0]), "+f"(c[1]), "+f"(c[2]), "+f"(c[3])
        : "r"(a[0]), "r"(a[1]), "r"(a[2]), "r"(a[3]), "r"(bb[0]), "r"(bb[1]));
}

__global__ __launch_bounds__(256, 2) void k_mma(const float* __restrict__ temp,
                                                float* __restrict__ C) {
    extern __shared__ char smem[];
    const uint32_t sb = (uint32_t)__cvta_generic_to_shared(smem);
    const int tid = threadIdx.x;
    const int wid = tid >> 5, lane = tid & 31;
    const int wr = wid >> 2;           // 0..1
    const int wc = wid & 3;            // 0..3
    const int b = blockIdx.z;
    const int n0 = blockIdx.y << 7;
    const int m0 = blockIdx.x << 7;

    const __nv_bfloat16* Ah = g_Ahi + ((long)b * NN + n0) * DK;
    const __nv_bfloat16* Al = g_Alo + ((long)b * NN + n0) * DK;
    const __nv_bfloat16* Bh = g_Bhi + ((long)b * MM + m0) * DK;
    const __nv_bfloat16* Bl = g_Blo + ((long)b * MM + m0) * DK;

    auto issue = [&](int stage, int k0) {
#pragma unroll
        for (int t = tid; t < 2048; t += 256) {
            const int tile = t >> 9;
            const int row = (t >> 2) & 127;
            const int ch = t & 3;
            const __nv_bfloat16* g =
                (tile == 0 ? Ah : tile == 1 ? Al : tile == 2 ? Bh : Bl) +
                (long)row * DK + k0 + ch * 8;
            cp16(sb + (uint32_t)(stage * STG2 + tile * TIL2 + row * ROWP2 + ch * 16), g);
        }
        CP_COMMIT();
    };

    float acc[4][4][4];
#pragma unroll
    for (int i = 0; i < 4; ++i)
#pragma unroll
        for (int j = 0; j < 4; ++j)
#pragma unroll
            for (int q = 0; q < 4; ++q) acc[i][j][q] = 0.f;

    const uint32_t aoff = (uint32_t)((lane & 15) * ROWP2 + ((lane >> 4) << 4));
    const int brow = (lane & 7) + ((lane >> 4) & 1) * 8;
    const uint32_t boff = (uint32_t)(brow * ROWP2 + (((lane >> 3) & 1) << 4));
    const int kcbase = wid & 1;

    uint32_t afr[4][4], bfrH[4][2], bfrL[4][2];

    auto ldA = [&](uint32_t tb, int kc) {
#pragma unroll
        for (int mt = 0; mt < 4; ++mt)
            ldmx4(tb + (uint32_t)((wr * 64 + mt * 16) * ROWP2 + kc * 32) + aoff,
                  afr[mt][0], afr[mt][1], afr[mt][2], afr[mt][3]);
    };
    auto ldB = [&](uint32_t tb, int kc, uint32_t bf[4][2]) {
#pragma unroll
        for (int p = 0; p < 2; ++p) {
            uint32_t r0, r1, r2, r3;
            ldmx4(tb + (uint32_t)((wc * 32 + p * 16) * ROWP2 + kc * 32) + boff,
                  r0, r1, r2, r3);
            bf[2 * p][0] = r0; bf[2 * p][1] = r1;
            bf[2 * p + 1][0] = r2; bf[2 * p + 1][1] = r3;
        }
    };
    auto domma = [&](uint32_t bf[4][2]) {
#pragma unroll
        for (int mt = 0; mt < 4; ++mt)
#pragma unroll
            for (int nt = 0; nt < 4; ++nt)
                mma16816(acc[mt][nt], afr[mt], bf[nt]);
    };

    issue(0, 0);
    int buf = 0;
#pragma unroll 1
    for (int it = 0; it < 16; ++it) {
        if (it + 1 < 16) {
            issue(buf ^ 1, (it + 1) * 32);
            CP_WAIT1();
        } else {
            CP_WAIT0();
        }
        __syncthreads();
        const uint32_t st = sb + (uint32_t)(buf * STG2);
#pragma unroll
        for (int k = 0; k < 2; ++k) {
            const int kc = k ^ kcbase;
            ldA(st, kc);                         // A hi
            ldB(st + 2 * TIL2, kc, bfrH);        // B hi
            ldB(st + 3 * TIL2, kc, bfrL);        // B lo
            domma(bfrH);                         // hi*hi
            domma(bfrL);                         // hi*lo
            ldA(st + TIL2, kc);                  // A lo (reuse buffer)
            domma(bfrH);                         // lo*hi
        }
        __syncthreads();
        buf ^= 1;
    }

    const float sc = 1.0f / (sqrtf((float)DK) * temp[b]);
    const int ib = wr * 64 + (lane >> 2);
    const int jb = wc * 32 + (lane & 3) * 2;
#pragma unroll
    for (int mt = 0; mt < 4; ++mt)
#pragma unroll
        for (int nt = 0; nt < 4; ++nt) {
            long base = (((long)(b << 10) + n0 + ib + mt * 16) << 10) + m0 + jb + nt * 8;
            *(float2*)&C[base] =
                make_float2(acc[mt][nt][0] * sc, acc[mt][nt][1] * sc);
            *(float2*)&C[base + (8 << 10)] =
                make_float2(acc[mt][nt][2] * sc, acc[mt][nt][3] * sc);
        }
}

// ============================================================
// Fused sinkhorn iteration: row-LSE (-> u) + column partials, one read.
// ============================================================
__global__ __launch_bounds__(256) void k_fused(const float* __restrict__ C, int first) {
    const int seg = blockIdx.x;   // 0..63
    const int b = blockIdx.y;     // 0..15
    const int t = threadIdx.x;    // 256
    const int wid = t >> 5, lane = t & 31;
    __shared__ float4 V4s[256];
    __shared__ float red[16][256];
    __shared__ float Ms[16];
    __shared__ float Us[16];

    V4s[t] = first ? make_float4(0.f, 0.f, 0.f, 0.f)
                   : ((const float4*)(g_V + (b << 10)))[t];
    __syncthreads();
    const float4 v4 = V4s[t];

    const float4* base = (const float4*)(C + ((long)b << 20) + ((long)seg << 14));
    float4 x[16];
#pragma unroll
    for (int i = 0; i < 16; ++i) {
        float4 c = base[(i << 8) + t];
        x[i] = make_float4(c.x + v4.x, c.y + v4.y, c.z + v4.z, c.w + v4.w);
    }

#pragma unroll
    for (int i = 0; i < 16; ++i)
        red[i][t] = fmaxf(fmaxf(x[i].x, x[i].y), fmaxf(x[i].z, x[i].w));
    __syncthreads();
#pragma unroll
    for (int rr = 0; rr < 2; ++rr) {
        const int r = 2 * wid + rr;
        float m = red[r][lane];
#pragma unroll
        for (int k = 1; k < 8; ++k) m = fmaxf(m, red[r][lane + 32 * k]);
#pragma unroll
        for (int o = 16; o; o >>= 1) m = fmaxf(m, __shfl_xor_sync(0xffffffffu, m, o));
        if (lane == 0) Ms[r] = fmaxf(m, 0.f);
    }
    __syncthreads();

    float mrow[16];
#pragma unroll
    for (int i = 0; i < 16; ++i) mrow[i] = Ms[i];
#pragma unroll
    for (int i = 0; i < 16; ++i) {
        float s = __expf(x[i].x - mrow[i]) + __expf(x[i].y - mrow[i]) +
                  __expf(x[i].z - mrow[i]) + __expf(x[i].w - mrow[i]);
        red[i][t] = s;
    }
    __syncthreads();
#pragma unroll
    for (int rr = 0; rr < 2; ++rr) {
        const int r = 2 * wid + rr;
        float s = red[r][lane];
#pragma unroll
        for (int k = 1; k < 8; ++k) s += red[r][lane + 32 * k];
#pragma unroll
        for (int o = 16; o; o >>= 1) s += __shfl_xor_sync(0xffffffffu, s, o);
        if (lane == 0) {
            float m = Ms[r];
            float u = -(m + logf(s + __expf(-m)));
            Us[r] = u;
            g_U[(b << 10) + (seg << 4) + r] = u;
        }
    }
    __syncthreads();

    float u0 = Us[0];
    float4 M = make_float4(x[0].x + u0, x[0].y + u0, x[0].z + u0, x[0].w + u0);
#pragma unroll
    for (int i = 1; i < 16; ++i) {
        float u = Us[i];
        M.x = fmaxf(M.x, x[i].x + u); M.y = fmaxf(M.y, x[i].y + u);
        M.z = fmaxf(M.z, x[i].z + u); M.w = fmaxf(M.w, x[i].w + u);
    }
    float4 S = make_float4(0.f, 0.f, 0.f, 0.f);
#pragma unroll
    for (int i = 0; i < 16; ++i) {
        float u = Us[i];
        S.x += __expf(x[i].x + u - M.x); S.y += __expf(x[i].y + u - M.y);
        S.z += __expf(x[i].z + u - M.z); S.w += __expf(x[i].w + u - M.w);
    }
    const long pidx = (((long)(b << 6) + seg) << 8) + t;
    ((float4*)g_PM)[pidx] =
        make_float4(M.x - v4.x, M.y - v4.y, M.z - v4.z, M.w - v4.w);
    ((float4*)g_PS)[pidx] = S;
}

// ============================================================
// Combine 64 segment partials per column: grid (32, NB) x 256.
// 8 threads/column x 8 segments, REGISTER TWO-PASS (no serial folds).
// ============================================================
__global__ __launch_bounds__(256) void k_colr() {
    const int b = blockIdx.y;
    const int c = threadIdx.x & 31;
    const int q = threadIdx.x >> 5;          // 0..7
    const int j = (blockIdx.x << 5) + c;
    __shared__ float Msm[8][32], Ssm[8][32];

    float mv[8], sv[8];
#pragma unroll
    for (int g = 0; g < 8; ++g) {
        const long p = (((long)(b << 6) + (q << 3) + g) << 10) + j;
        mv[g] = g_PM[p];
        sv[g] = g_PS[p];
    }
    float M = mv[0];
#pragma unroll
    for (int g = 1; g < 8; ++g) M = fmaxf(M, mv[g]);
    float S = 0.f;
#pragma unroll
    for (int g = 0; g < 8; ++g) S += sv[g] * __expf(mv[g] - M);
    Msm[q][c] = M;
    Ssm[q][c] = S;
    __syncthreads();
    if (q == 0) {
        float m2[8], s2[8];
#pragma unroll
        for (int g = 0; g < 8; ++g) { m2[g] = Msm[g][c]; s2[g] = Ssm[g][c]; }
        float MM2 = m2[0];
#pragma unroll
        for (int g = 1; g < 8; ++g) MM2 = fmaxf(MM2, m2[g]);
        MM2 = fmaxf(MM2, 0.f);   // slack row
        float SS = __expf(-MM2);
#pragma unroll
        for (int g = 0; g < 8; ++g) SS += s2[g] * __expf(m2[g] - MM2);
        g_V[(b << 10) + j] = -(MM2 + logf(SS));
    }
}

// ============================================================
// Finalize
// ============================================================
__global__ __launch_bounds__(256) void k_final(float* __restrict__ C,
                                               const float* __restrict__ tgt) {
    const int gb = blockIdx.x;
    const int b = gb >> 7;
    const int row = ((gb & 127) << 3) + (threadIdx.x >> 5);
    const int lane = threadIdx.x & 31;
    __shared__ float4 Vs4[256], T04[256], T14[256], T24[256];
    const float* tb = tgt + (long)b * 3 * MM;
    Vs4[threadIdx.x] = ((const float4*)(g_V + (b << 10)))[threadIdx.x];
    T04[threadIdx.x] = ((const float4*)tb)[threadIdx.x];
    T14[threadIdx.x] = ((const float4*)(tb + MM))[threadIdx.x];
    T24[threadIdx.x] = ((const float4*)(tb + 2 * MM))[threadIdx.x];
    __syncthreads();
    float4* rp = (float4*)(C + (((long)(b << 10) + row) << 10));
    const float u = g_U[(b << 10) + row];
    float4 p[8];
    float s0 = 0.f, s1 = 0.f, s2 = 0.f, s3 = 0.f;
#pragma unroll
    for (int k = 0; k < 8; ++k) {
        float4 c = rp[lane + (k << 5)];
        float4 v = Vs4[lane + (k << 5)];
        p[k].x = __expf(c.x + u + v.x);
        p[k].y = __expf(c.y + u + v.y);
        p[k].z = __expf(c.z + u + v.z);
        p[k].w = __expf(c.w + u + v.w);
        s0 += p[k].x; s1 += p[k].y; s2 += p[k].z; s3 += p[k].w;
    }
    float sum = (s0 + s1) + (s2 + s3);
#pragma unroll
    for (int o = 16; o; o >>= 1) sum += __shfl_xor_sync(0xffffffffu, sum, o);
    const float inv = 1.f / (sum + 1e-8f);
    float w0 = 0.f, w1 = 0.f, w2 = 0.f;
#pragma unroll
    for (int k = 0; k < 8; ++k) {
        int j4 = lane + (k << 5);
        float4 pn = make_float4(p[k].x * inv, p[k].y * inv, p[k].z * inv, p[k].w * inv);
        rp[j4] = pn;
        float4 t0 = T04[j4], t1 = T14[j4], t2 = T24[j4];
        w0 = fmaf(pn.x, t0.x, fmaf(pn.y, t0.y, fmaf(pn.z, t0.z, fmaf(pn.w, t0.w, w0))));
        w1 = fmaf(pn.x, t1.x, fmaf(pn.y, t1.y, fmaf(pn.z, t1.z, fmaf(pn.w, t1.w, w1))));
        w2 = fmaf(pn.x, t2.x, fmaf(pn.y, t2.y, fmaf(pn.z, t2.z, fmaf(pn.w, t2.w, w2))));
    }
#pragma unroll
    for (int o = 16; o; o >>= 1) {
        w0 += __shfl_xor_sync(0xffffffffu, w0, o);
        w1 += __shfl_xor_sync(0xffffffffu, w1, o);
        w2 += __shfl_xor_sync(0xffffffffu, w2, o);
    }
    if (lane == 0) {
        g_W[(b << 10) + row] = sum;
        g_WT[b * 3 * NN + row] = w0;
        g_WT[b * 3 * NN + NN + row] = w1;
        g_WT[b * 3 * NN + 2 * NN + row] = w2;
    }
}

// ============================================================
// Per-batch weighted Procrustes (Horn quaternion via 4x4 Jacobi, fp64).
// ============================================================
__global__ __launch_bounds__(256) void k_proc(const float* __restrict__ src,
                                              float* __restrict__ out) {
    const int b = blockIdx.x;
    const int tid = threadIdx.x;
    __shared__ float sm[256 * 12];
    __shared__ float cent[8];
    const float* sb = src + (long)b * 3 * NN;
    const float* wb = g_W + (b << 10);
    const float* wtb = g_WT + b * 3 * NN;

    float ws = 0, s0 = 0, s1 = 0, s2 = 0, t0 = 0, t1 = 0, t2 = 0;
    for (int i = tid; i < NN; i += 256) {
        float w = wb[i];
        ws += w;
        s0 = fmaf(sb[i], w, s0);
        s1 = fmaf(sb[NN + i], w, s1);
        s2 = fmaf(sb[2 * NN + i], w, s2);
        t0 = fmaf(wtb[i], w, t0);
        t1 = fmaf(wtb[NN + i], w, t1);
        t2 = fmaf(wtb[2 * NN + i], w, t2);
    }
    sm[tid * 12 + 0] = ws; sm[tid * 12 + 1] = s0; sm[tid * 12 + 2] = s1;
    sm[tid * 12 + 3] = s2; sm[tid * 12 + 4] = t0; sm[tid * 12 + 5] = t1;
    sm[tid * 12 + 6] = t2;
    __syncthreads();
    for (int st = 128; st; st >>= 1) {
        if (tid < st)
            for (int k = 0; k < 7; ++k) sm[tid * 12 + k] += sm[(tid + st) * 12 + k];
        __syncthreads();
    }
    if (tid == 0) {
        float inv = 1.f / (sm[0] + 1e-8f);
        cent[6] = inv;
        for (int c = 0; c < 3; ++c) { cent[c] = sm[1 + c] * inv; cent[3 + c] = sm[4 + c] * inv; }
    }
    __syncthreads();
    const float inv = cent[6];
    const float sc0 = cent[0], sc1 = cent[1], sc2 = cent[2];
    const float tc0 = cent[3], tc1 = cent[4], tc2 = cent[5];

    float h[9];
#pragma unroll
    for (int k = 0; k < 9; ++k) h[k] = 0.f;
    for (int i = tid; i < NN; i += 256) {
        float wn = wb[i] * inv;
        float a0 = sb[i] - sc0, a1 = sb[NN + i] - sc1, a2 = sb[2 * NN + i] - sc2;
        float b0 = (wtb[i] - tc0) * wn;
        float b1 = (wtb[NN + i] - tc1) * wn;
        float b2 = (wtb[2 * NN + i] - tc2) * wn;
        h[0] = fmaf(a0, b0, h[0]); h[1] = fmaf(a0, b1, h[1]); h[2] = fmaf(a0, b2, h[2]);
        h[3] = fmaf(a1, b0, h[3]); h[4] = fmaf(a1, b1, h[4]); h[5] = fmaf(a1, b2, h[5]);
        h[6] = fmaf(a2, b0, h[6]); h[7] = fmaf(a2, b1, h[7]); h[8] = fmaf(a2, b2, h[8]);
    }
    __syncthreads();
    for (int k = 0; k < 9; ++k) sm[tid * 12 + k] = h[k];
    __syncthreads();
    for (int st = 128; st; st >>= 1) {
        if (tid < st)
            for (int k = 0; k < 9; ++k) sm[tid * 12 + k] += sm[(tid + st) * 12 + k];
        __syncthreads();
    }

    if (tid == 0) {
        double Sxx = sm[0], Sxy = sm[1], Sxz = sm[2];
        double Syx = sm[3], Syy = sm[4], Syz = sm[5];
        double Szx = sm[6], Szy = sm[7], Szz = sm[8];
        double A4[4][4], V4[4][4];
        A4[0][0] = Sxx + Syy + Szz;
        A4[0][1] = Syz - Szy; A4[0][2] = Szx - Sxz; A4[0][3] = Sxy - Syx;
        A4[1][1] = Sxx - Syy - Szz;
        A4[1][2] = Sxy + Syx; A4[1][3] = Szx + Sxz;
        A4[2][2] = -Sxx + Syy - Szz;
        A4[2][3] = Syz + Szy;
        A4[3][3] = -Sxx - Syy + Szz;
        A4[1][0] = A4[0][1]; A4[2][0] = A4[0][2]; A4[3][0] = A4[0][3];
        A4[2][1] = A4[1][2]; A4[3][1] = A4[1][3]; A4[3][2] = A4[2][3];
        for (int i = 0; i < 4; ++i)
            for (int j = 0; j < 4; ++j) V4[i][j] = (i == j) ? 1.0 : 0.0;
        for (int sw = 0; sw < 8; ++sw) {
            for (int p = 0; p < 3; ++p)
                for (int q = p + 1; q < 4; ++q) {
                    double apq = A4[p][q];
                    if (fabs(apq) < 1e-300) continue;
                    double tau = (A4[q][q] - A4[p][p]) / (2.0 * apq);
                    double tt = (tau >= 0 ? 1.0 : -1.0) / (fabs(tau) + sqrt(1.0 + tau * tau));
                    double cc = 1.0 / sqrt(1.0 + tt * tt);
                    double ssn = tt * cc;
                    for (int k = 0; k < 4; ++k) {
                        double r1 = A4[p][k], r2 = A4[q][k];
                        A4[p][k] = cc * r1 - ssn * r2;
                        A4[q][k] = ssn * r1 + cc * r2;
                    }
                    for (int k = 0; k < 4; ++k) {
                        double c1 = A4[k][p], c2 = A4[k][q];
                        A4[k][p] = cc * c1 - ssn * c2;
                        A4[k][q] = ssn * c1 + cc * c2;
                    }
                    for (int k = 0; k < 4; ++k) {
                        double v1 = V4[k][p], v2 = V4[k][q];
                        V4[k][p] = cc * v1 - ssn * v2;
                        V4[k][q] = ssn * v1 + cc * v2;
                    }
                }
        }
        int best = 0;
        for (int k = 1; k < 4; ++k) if (A4[k][k] > A4[best][best]) best = k;
        double q0 = V4[0][best], qx = V4[1][best], qy = V4[2][best], qz = V4[3][best];
        double qn = 1.0 / sqrt(q0 * q0 + qx * qx + qy * qy + qz * qz);
        q0 *= qn; qx *= qn; qy *= qn; qz *= qn;
        double R_[3][3];
        R_[0][0] = 1 - 2 * (qy * qy + qz * qz);
        R_[0][1] = 2 * (qx * qy - q0 * qz);
        R_[0][2] = 2 * (qx * qz + q0 * qy);
        R_[1][0] = 2 * (qx * qy + q0 * qz);
        R_[1][1] = 1 - 2 * (qx * qx + qz * qz);
        R_[1][2] = 2 * (qy * qz - q0 * qx);
        R_[2][0] = 2 * (qx * qz - q0 * qy);
        R_[2][1] = 2 * (qy * qz + q0 * qx);
        R_[2][2] = 1 - 2 * (qx * qx + qy * qy);
        double H_[3][3] = {{Sxx, Sxy, Sxz}, {Syx, Syy, Syz}, {Szx, Szy, Szz}};
        double tr1 = 0, tr2 = 0;
        for (int i = 0; i < 3; ++i)
            for (int k = 0; k < 3; ++k) {
                tr1 += R_[i][k] * H_[k][i];
                tr2 += R_[k][i] * H_[k][i];
            }
        if (tr2 > tr1) {
            for (int i = 0; i < 3; ++i)
                for (int k = i + 1; k < 3; ++k) {
                    double tmp = R_[i][k]; R_[i][k] = R_[k][i]; R_[k][i] = tmp;
                }
        }
        double scv[3] = {sc0, sc1, sc2}, tcv[3] = {tc0, tc1, tc2};
        for (int i = 0; i < 3; ++i)
            for (int k = 0; k < 3; ++k)
                out[b * 9 + i * 3 + k] = (float)R_[i][k];
        for (int c = 0; c < 3; ++c) {
            double tv = tcv[c];
            for (int k = 0; k < 3; ++k) tv -= R_[c][k] * scv[k];
            out[NB * 9 + b * 3 + c] = (float)tv;
        }
    }
}

// ============================================================
extern "C" void kernel_launch(void* const* d_in, const int* in_sizes, int n_in,
                              void* d_out, int out_size) {
    const float* srcE = (const float*)d_in[0];
    const float* tgtE = (const float*)d_in[1];
    const float* src  = (const float*)d_in[2];
    const float* tgt  = (const float*)d_in[3];
    const float* temp = (const float*)d_in[4];
    float* out = (float*)d_out;
    float* aff = out + NB * 9 + NB * 3;

    (void)in_sizes; (void)n_in; (void)out_size;

    const int SMEM_SZ = 2 * STG2;   // 81920 per CTA -> 2 CTAs/SM
    static int configured = 0;
    if (!configured) {
        cudaFuncSetAttribute(k_mma, cudaFuncAttributeMaxDynamicSharedMemorySize, SMEM_SZ);
        configured = 1;
    }

    k_conv<<<dim3(32, 16, 32), 256>>>(srcE, tgtE);
    k_mma<<<dim3(8, 8, NB), 256, SMEM_SZ>>>(temp, aff);
    for (int it = 0; it < 5; ++it) {
        k_fused<<<dim3(64, NB), 256>>>(aff, it == 0);
        k_colr<<<dim3(32, NB), 256>>>();
    }
    k_final<<<2048, 256>>>(aff, tgt);
    k_proc<<<NB, 256>>>(src, out);
}